// round 2
// baseline (speedup 1.0000x reference)
#include <cuda_runtime.h>
#include <cstdint>
#include <cstddef>

#define B_   1024
#define NT   128
#define NY   128
#define C_   512
#define EOS_ 1

// Compact gathered coefficients: G[b][t][{pC,pI}][j], t slot 127 unused (pad for prefetch).
// 1024 * 128 * 2 * 128 floats = 128 MiB scratch (device .bss, zero-init).
__device__ float4 g_G4[(size_t)B_ * NT * 2 * (NY / 4)];

// Padded SMEM row stride (floats): 516 = multiple of 4 (16B cp.async alignment),
// 516 % 32 == 4 -> gather reads are at worst 2-way bank conflicted.
#define RSTRIDE 516

// ---------------------------------------------------------------------------
// Phase 1: per-batch gather/transpose.
// CTA = one batch. Stream pred/I rows (16-row groups, double buffered cp.async.cg),
// skipping 16B chunks no target ever touches, then gather columns target[t] and
// write p_C = R0[j]*pred_g, p_I = R1[j]*I_g (R1[127]:=1) to compact G.
// ---------------------------------------------------------------------------
__global__ __launch_bounds__(256, 3) void gather_kernel(
    const float* __restrict__ pred, const float* __restrict__ R,
    const float* __restrict__ I, const int* __restrict__ target) {
  extern __shared__ float stage[];  // [2][16 * RSTRIDE]
  __shared__ int tgt_s[NT];
  __shared__ float rC[NY], rI[NY];
  __shared__ unsigned mask_s[4];    // 128-bit mask over 16B chunks (4 floats each)

  const int b = blockIdx.x;
  const int tid = threadIdx.x;
  float* g_G = (float*)g_G4;

  if (tid < 4) mask_s[tid] = 0u;
  if (tid < NT) {
    tgt_s[tid] = target[b * NT + tid];
  }
  if (tid < NY) {
    int base = (b * NY + tid) * 3;
    rC[tid] = R[base];
    rI[tid] = (tid == NY - 1) ? 1.0f : R[base + 1];
  }
  __syncthreads();
  if (tid < NT - 1) {  // only t=0..126 are gathered
    int cbit = tgt_s[tid] >> 2;  // 16B chunk index 0..127
    atomicOr(&mask_s[cbit >> 5], 1u << (cbit & 31));
  }
  __syncthreads();

  // Fixed per-thread column chunk: cc = tid & 127 (since 256*p = 0 mod 128).
  const int cc = tid & 127;
  const unsigned on = (mask_s[cc >> 5] >> (cc & 31)) & 1u;
  const int rbase = tid >> 7;  // 0 or 1

  auto issue = [&](int g) {
    const int arr = g >> 3;            // 0 = pred, 1 = I
    const int r0 = (g & 7) * 16;       // first row of group
    const float* src = (arr ? I : pred) + ((size_t)b * NY + r0) * C_ + cc * 4;
    float* buf = stage + (g & 1) * (16 * RSTRIDE) + cc * 4;
#pragma unroll
    for (int p = 0; p < 8; ++p) {
      const int r = rbase + 2 * p;
      unsigned sa = (unsigned)__cvta_generic_to_shared(buf + r * RSTRIDE);
      const float* gp = src + (size_t)r * C_;
      asm volatile(
          "{ .reg .pred p0; setp.ne.u32 p0, %0, 0;"
          " @p0 cp.async.cg.shared.global [%1], [%2], 16; }"
          :: "r"(on), "r"(sa), "l"(gp) : "memory");
    }
    asm volatile("cp.async.commit_group;" ::: "memory");
  };

  issue(0);
  issue(1);

  const int jloc = tid & 15;
  const int tb = tid >> 4;  // 0..15
  for (int g = 0; g < 16; ++g) {
    if (g == 15) asm volatile("cp.async.wait_group 0;" ::: "memory");
    else         asm volatile("cp.async.wait_group 1;" ::: "memory");
    __syncthreads();

    const int arr = g >> 3;
    const int r0 = (g & 7) * 16;
    const int j = r0 + jloc;
    const float sc = arr ? rI[j] : rC[j];
    const float* buf = stage + (g & 1) * (16 * RSTRIDE) + jloc * RSTRIDE;
#pragma unroll
    for (int p = 0; p < 8; ++p) {
      const int t = tb + 16 * p;
      if (t < NT - 1) {
        const int tt = tgt_s[t];
        const float v = buf[tt];
        g_G[(((size_t)b * NT + t) * 2 + arr) * NY + j] = v * sc;
      }
    }
    __syncthreads();
    if (g + 2 < 16) issue(g + 2);
  }
}

// ---------------------------------------------------------------------------
// Phase 2: warp per batch; lane l owns j = 4l..4l+3.
// Linear recurrence x[j] = a[j] + d[j]*x[j-1] via affine (A,D) warp scan.
// ---------------------------------------------------------------------------
__global__ __launch_bounds__(128) void scan_kernel(
    const float* __restrict__ R, const int* __restrict__ target,
    float* __restrict__ out) {
  const int l = threadIdx.x & 31;
  const int w = threadIdx.x >> 5;
  const int b = blockIdx.x * 4 + w;
  const unsigned FULL = 0xffffffffu;

  // EOS bitmasks over t (broadcast to all lanes via ballot)
  unsigned em[4];
#pragma unroll
  for (int m = 0; m < 4; ++m) {
    const int tg = target[b * NT + l + 32 * m];
    em[m] = __ballot_sync(FULL, tg == EOS_);
  }

  // R2[j] for owned j's; dsh = R2[j-1] (shifted by one position)
  float r2[4];
#pragma unroll
  for (int k = 0; k < 4; ++k)
    r2[k] = R[((size_t)b * NY + 4 * l + k) * 3 + 2];
  const float r2p = __shfl_up_sync(FULL, r2[3], 1);
  const float dsh0 = (l == 0) ? 1.0f : r2p;  // d at j=0 is always 1

  // row0[j] = prod_{k=1..j} (eos0 ? 1 : R2[k])
  const bool eos0 = em[0] & 1u;
  const float m0v = (l == 0) ? 1.0f : (eos0 ? 1.0f : r2[0]);
  const float m1v = eos0 ? 1.0f : r2[1];
  const float m2v = eos0 ? 1.0f : r2[2];
  const float m3v = eos0 ? 1.0f : r2[3];
  const float P0 = m0v, P1 = P0 * m1v, P2 = P1 * m2v, P3 = P2 * m3v;
  float Pw = P3;
#pragma unroll
  for (int off = 1; off < 32; off <<= 1) {
    const float Po = __shfl_up_sync(FULL, Pw, off);
    if (l >= off) Pw *= Po;
  }
  float pin = __shfl_up_sync(FULL, Pw, 1);
  if (l == 0) pin = 1.0f;
  float row0 = P0 * pin, row1 = P1 * pin, row2 = P2 * pin, row3 = P3 * pin;

  const float4* __restrict__ G4 = g_G4;
  size_t base0 = ((size_t)b * NT) * 64 + l;  // ((b*NT+0)*2+0)*32 + l
  float4 cpc = G4[base0];
  float4 cpi = G4[base0 + 32];

  for (int i = 0; i < NT - 1; ++i) {
    // prefetch next step (slot i+1=127 exists as padding)
    const size_t bn = (((size_t)b * NT + i + 1) * 2) * 32 + l;
    const float4 npc = G4[bn];
    const float4 npi = G4[bn + 32];

    const int ts = i + 1;
    const unsigned ew = (ts & 64) ? ((ts & 32) ? em[3] : em[2])
                                  : ((ts & 32) ? em[1] : em[0]);
    const bool eos = (ew >> (ts & 31)) & 1u;
    const float d0 = eos ? 1.0f : dsh0;
    const float d1 = eos ? 1.0f : r2[0];
    const float d2 = eos ? 1.0f : r2[1];
    const float d3 = eos ? 1.0f : r2[2];

    // a_full[j] = row[j-1]*pC[j-1] + row[j]*pI[j]   (j=0: new0 = row[0]*pI[0])
    const float q3 = row3 * cpc.w;
    float qp = __shfl_up_sync(FULL, q3, 1);
    if (l == 0) qp = 0.0f;
    const float a0 = fmaf(row0, cpi.x, qp);
    const float a1 = fmaf(row1, cpi.y, row0 * cpc.x);
    const float a2 = fmaf(row2, cpi.z, row1 * cpc.y);
    const float a3 = fmaf(row3, cpi.w, row2 * cpc.z);

    // local affine prefixes: x[k] = A[k] + D[k] * x_in
    const float A0 = a0, D0 = d0;
    const float A1 = fmaf(d1, A0, a1), D1 = d1 * D0;
    const float A2 = fmaf(d2, A1, a2), D2 = d2 * D1;
    const float A3 = fmaf(d3, A2, a3), D3 = d3 * D2;

    // inclusive warp scan of (A,D) under affine composition
    float As = A3, Ds = D3;
#pragma unroll
    for (int off = 1; off < 32; off <<= 1) {
      const float Ao = __shfl_up_sync(FULL, As, off);
      const float Do = __shfl_up_sync(FULL, Ds, off);
      if (l >= off) { As = fmaf(Ds, Ao, As); Ds *= Do; }
    }
    float xin = __shfl_up_sync(FULL, As, 1);
    if (l == 0) xin = 0.0f;

    row0 = fmaf(D0, xin, A0);
    row1 = fmaf(D1, xin, A1);
    row2 = fmaf(D2, xin, A2);
    row3 = As;  // = A3 + D3*xin

    cpc = npc; cpi = npi;
  }

  if (l == 31) out[b] = row3;
}

// ---------------------------------------------------------------------------
extern "C" void kernel_launch(void* const* d_in, const int* in_sizes, int n_in,
                              void* d_out, int out_size) {
  const float* pred   = (const float*)d_in[0];
  const float* R      = (const float*)d_in[1];
  const float* I      = (const float*)d_in[2];
  const int*   target = (const int*)d_in[3];

  const int smem = 2 * 16 * RSTRIDE * (int)sizeof(float);  // 66,048 B
  cudaFuncSetAttribute(gather_kernel,
                       cudaFuncAttributeMaxDynamicSharedMemorySize, smem);

  gather_kernel<<<B_, 256, smem>>>(pred, R, I, target);
  scan_kernel<<<B_ / 4, 128>>>(R, target, (float*)d_out);
}

// round 3
// speedup vs baseline: 1.3445x; 1.3445x over previous
#include <cuda_runtime.h>
#include <cstdint>
#include <cstddef>

#define B_   1024
#define NT   128
#define NY   128
#define C_   512
#define EOS_ 1

// Compact gathered coefficients: G[b][t][{pC,pI}][j], t slot 127 unused (pad for prefetch).
// 1024 * 128 * 2 * 128 floats = 128 MiB scratch (device .bss, zero-init).
__device__ float4 g_G4[(size_t)B_ * NT * 2 * (NY / 4)];

// Padded SMEM row stride (floats): 516 = multiple of 4 (16B cp.async alignment),
// 516 % 32 == 4 -> gather reads are at worst mildly bank conflicted.
#define RSTRIDE 516

// ---------------------------------------------------------------------------
// Phase 1: gather/transpose. One CTA handles ONE (batch, array) pair:
//   blockIdx.x = b*2 + arr   (arr 0 = pred -> pC, arr 1 = I -> pI)
// Stream rows in 16-row groups (double-buffered cp.async.cg), skipping 16B
// chunks no target ever touches, then gather columns target[t], scale, and
// write to compact G.
// ---------------------------------------------------------------------------
__global__ __launch_bounds__(256, 3) void gather_kernel(
    const float* __restrict__ pred, const float* __restrict__ R,
    const float* __restrict__ I, const int* __restrict__ target) {
  extern __shared__ float stage[];  // [2][16 * RSTRIDE]
  __shared__ int tgt_s[NT];
  __shared__ float rS[NY];
  __shared__ unsigned mask_s[4];    // 128-bit mask over 16B chunks (4 floats each)

  const int b   = blockIdx.x >> 1;
  const int arr = blockIdx.x & 1;
  const int tid = threadIdx.x;
  float* g_G = (float*)g_G4;

  if (tid < 4) mask_s[tid] = 0u;
  if (tid < NT) tgt_s[tid] = target[b * NT + tid];
  if (tid < NY) {
    const int base = (b * NY + tid) * 3;
    rS[tid] = arr ? ((tid == NY - 1) ? 1.0f : R[base + 1]) : R[base];
  }
  __syncthreads();
  if (tid < NT - 1) {  // only t=0..126 are gathered
    const int cbit = tgt_s[tid] >> 2;  // 16B chunk index 0..127
    atomicOr(&mask_s[cbit >> 5], 1u << (cbit & 31));
  }
  __syncthreads();

  // Fixed per-thread column chunk: cc = tid & 127.
  const int cc = tid & 127;
  const unsigned on = (mask_s[cc >> 5] >> (cc & 31)) & 1u;
  const int rbase = tid >> 7;  // 0 or 1
  const float* __restrict__ src_arr = arr ? I : pred;

  auto issue = [&](int g) {
    const int r0 = g * 16;  // first row (j) of group
    const float* src = src_arr + ((size_t)b * NY + r0) * C_ + cc * 4;
    float* buf = stage + (g & 1) * (16 * RSTRIDE) + cc * 4;
#pragma unroll
    for (int p = 0; p < 8; ++p) {
      const int r = rbase + 2 * p;
      unsigned sa = (unsigned)__cvta_generic_to_shared(buf + r * RSTRIDE);
      const float* gp = src + (size_t)r * C_;
      asm volatile(
          "{ .reg .pred p0; setp.ne.u32 p0, %0, 0;"
          " @p0 cp.async.cg.shared.global [%1], [%2], 16; }"
          :: "r"(on), "r"(sa), "l"(gp) : "memory");
    }
    asm volatile("cp.async.commit_group;" ::: "memory");
  };

  issue(0);
  issue(1);

  const int jloc = tid & 15;
  const int tb = tid >> 4;  // 0..15
  for (int g = 0; g < 8; ++g) {
    if (g == 7) asm volatile("cp.async.wait_group 0;" ::: "memory");
    else        asm volatile("cp.async.wait_group 1;" ::: "memory");
    __syncthreads();

    const int r0 = g * 16;
    const int j = r0 + jloc;
    const float sc = rS[j];
    const float* buf = stage + (g & 1) * (16 * RSTRIDE) + jloc * RSTRIDE;
#pragma unroll
    for (int p = 0; p < 8; ++p) {
      const int t = tb + 16 * p;
      if (t < NT - 1) {
        const int tt = tgt_s[t];
        const float v = buf[tt];
        g_G[(((size_t)b * NT + t) * 2 + arr) * NY + j] = v * sc;
      }
    }
    __syncthreads();
    if (g + 2 < 8) issue(g + 2);
  }
}

// ---------------------------------------------------------------------------
// Phase 2: warp per batch; lane l owns j = 4l..4l+3.
// Linear recurrence x[j] = a[j] + d[j]*x[j-1] via affine (A,D) warp scan.
// Coefficient rows stream through a per-warp cp.async SMEM ring, prefetched
// PF=14 steps ahead to fully hide DRAM latency.
// ---------------------------------------------------------------------------
#define PF 14

__global__ __launch_bounds__(128) void scan_kernel(
    const float* __restrict__ R, const int* __restrict__ target,
    float* __restrict__ out) {
  extern __shared__ float ring[];  // [4 warps][16 slots][256 floats] = 64 KB
  const int l = threadIdx.x & 31;
  const int w = threadIdx.x >> 5;
  const int b = blockIdx.x * 4 + w;
  const unsigned FULL = 0xffffffffu;

  float* wring = ring + w * (16 * 256);
  const float* __restrict__ gG = (const float*)g_G4;
  const size_t gbase = (size_t)b * NT * 256;

  auto issue_row = [&](int r) {
    const float* s1 = gG + gbase + (size_t)r * 256 + l * 4;
    float* d1 = wring + (r & 15) * 256 + l * 4;
    unsigned da = (unsigned)__cvta_generic_to_shared(d1);
    asm volatile(
        "cp.async.cg.shared.global [%0], [%1], 16;\n"
        "cp.async.cg.shared.global [%2], [%3], 16;\n"
        :: "r"(da), "l"(s1), "r"(da + 512), "l"(s1 + 128) : "memory");
    asm volatile("cp.async.commit_group;" ::: "memory");
  };

  // Prologue: prefetch rows 0..PF-1.
#pragma unroll
  for (int k = 0; k < PF; ++k) issue_row(k);

  // EOS bitmasks over t (broadcast to all lanes via ballot)
  unsigned em[4];
#pragma unroll
  for (int m = 0; m < 4; ++m) {
    const int tg = target[b * NT + l + 32 * m];
    em[m] = __ballot_sync(FULL, tg == EOS_);
  }

  // R2[j] for owned j's; dsh0 = R2[j-1] at j=4l (1 for lane 0).
  float r2[4];
#pragma unroll
  for (int k = 0; k < 4; ++k)
    r2[k] = R[((size_t)b * NY + 4 * l + k) * 3 + 2];
  const float r2p = __shfl_up_sync(FULL, r2[3], 1);
  const float dsh0 = (l == 0) ? 1.0f : r2p;

  // row0[j] = prod_{k=1..j} (eos0 ? 1 : R2[k])
  const bool eos0 = em[0] & 1u;
  const float m0v = (l == 0) ? 1.0f : (eos0 ? 1.0f : r2[0]);
  const float m1v = eos0 ? 1.0f : r2[1];
  const float m2v = eos0 ? 1.0f : r2[2];
  const float m3v = eos0 ? 1.0f : r2[3];
  const float P0 = m0v, P1 = P0 * m1v, P2 = P1 * m2v, P3 = P2 * m3v;
  float Pw = P3;
#pragma unroll
  for (int off = 1; off < 32; off <<= 1) {
    const float Po = __shfl_up_sync(FULL, Pw, off);
    if (l >= off) Pw *= Po;
  }
  float pin = __shfl_up_sync(FULL, Pw, 1);
  if (l == 0) pin = 1.0f;
  float row0 = P0 * pin, row1 = P1 * pin, row2 = P2 * pin, row3 = P3 * pin;

  // Row 0 ready?  After PF commits, allow PF-1 pending -> oldest (row 0) done.
  asm volatile("cp.async.wait_group 13;" ::: "memory");
  float4 cpc = *(const float4*)(wring + 0 * 256 + l * 4);
  float4 cpi = *(const float4*)(wring + 0 * 256 + 128 + l * 4);

  for (int i = 0; i < NT - 1; ++i) {
    // Keep the pipeline primed: issue row i+PF (pad row 127 exists in G).
    const int rf = i + PF;
    if (rf <= 127) issue_row(rf);
    else asm volatile("cp.async.commit_group;" ::: "memory");

    // Rows <= i+1 complete after this wait (PF-1 = 13 newest may be pending).
    asm volatile("cp.async.wait_group 13;" ::: "memory");
    const int slot = (i + 1) & 15;
    const float4 npc = *(const float4*)(wring + slot * 256 + l * 4);
    const float4 npi = *(const float4*)(wring + slot * 256 + 128 + l * 4);

    const int ts = i + 1;
    const unsigned ew = (ts & 64) ? ((ts & 32) ? em[3] : em[2])
                                  : ((ts & 32) ? em[1] : em[0]);
    const bool eos = (ew >> (ts & 31)) & 1u;
    const float d0 = eos ? 1.0f : dsh0;
    const float d1 = eos ? 1.0f : r2[0];
    const float d2 = eos ? 1.0f : r2[1];
    const float d3 = eos ? 1.0f : r2[2];

    // a_full[j] = row[j-1]*pC[j-1] + row[j]*pI[j]   (j=0: new0 = row[0]*pI[0])
    const float q3 = row3 * cpc.w;
    float qp = __shfl_up_sync(FULL, q3, 1);
    if (l == 0) qp = 0.0f;
    const float a0 = fmaf(row0, cpi.x, qp);
    const float a1 = fmaf(row1, cpi.y, row0 * cpc.x);
    const float a2 = fmaf(row2, cpi.z, row1 * cpc.y);
    const float a3 = fmaf(row3, cpi.w, row2 * cpc.z);

    // local affine prefixes: x[k] = A[k] + D[k] * x_in
    const float A0 = a0, D0 = d0;
    const float A1 = fmaf(d1, A0, a1), D1 = d1 * D0;
    const float A2 = fmaf(d2, A1, a2), D2 = d2 * D1;
    const float A3 = fmaf(d3, A2, a3), D3 = d3 * D2;

    // inclusive warp scan of (A,D) under affine composition
    float As = A3, Ds = D3;
#pragma unroll
    for (int off = 1; off < 32; off <<= 1) {
      const float Ao = __shfl_up_sync(FULL, As, off);
      const float Do = __shfl_up_sync(FULL, Ds, off);
      if (l >= off) { As = fmaf(Ds, Ao, As); Ds *= Do; }
    }
    float xin = __shfl_up_sync(FULL, As, 1);
    if (l == 0) xin = 0.0f;

    row0 = fmaf(D0, xin, A0);
    row1 = fmaf(D1, xin, A1);
    row2 = fmaf(D2, xin, A2);
    row3 = As;  // = A3 + D3*xin

    cpc = npc; cpi = npi;
  }

  if (l == 31) out[b] = row3;
}

// ---------------------------------------------------------------------------
extern "C" void kernel_launch(void* const* d_in, const int* in_sizes, int n_in,
                              void* d_out, int out_size) {
  const float* pred   = (const float*)d_in[0];
  const float* R      = (const float*)d_in[1];
  const float* I      = (const float*)d_in[2];
  const int*   target = (const int*)d_in[3];

  const int smem_g = 2 * 16 * RSTRIDE * (int)sizeof(float);  // 66,048 B
  cudaFuncSetAttribute(gather_kernel,
                       cudaFuncAttributeMaxDynamicSharedMemorySize, smem_g);
  const int smem_s = 4 * 16 * 256 * (int)sizeof(float);      // 65,536 B
  cudaFuncSetAttribute(scan_kernel,
                       cudaFuncAttributeMaxDynamicSharedMemorySize, smem_s);

  gather_kernel<<<B_ * 2, 256, smem_g>>>(pred, R, I, target);
  scan_kernel<<<B_ / 4, 128, smem_s>>>(R, target, (float*)d_out);
}